// round 2
// baseline (speedup 1.0000x reference)
#include <cuda_runtime.h>
#include <cuda_bf16.h>
#include <math.h>

// ---------------- Problem constants ----------------
#define BB      2
#define LL      4096
#define DMODEL  1024
#define DSSM    2048
#define DSTATE  128
#define DCONV   4
#define NH      32
#define HD      64
#define CONVDIM (DSSM + 2*DSTATE)          // 2304
#define DPROJ   (2*DSSM + 2*DSTATE + NH)   // 4384
#define EPSV    1e-5f

#define ROWS    (BB*LL)                    // 8192

// ---------------- Scratch (static device arrays; no allocation) ----------------
__device__ float g_zxbcdt[(size_t)ROWS * DPROJ];   // in-proj output
__device__ float g_xbc[(size_t)ROWS * CONVDIM];    // conv+silu output
__device__ float g_dt[(size_t)ROWS * NH];          // softplus(dt)
__device__ float g_dA[(size_t)ROWS * NH];          // exp(dt*A)
__device__ float g_y[(size_t)ROWS * DSSM];         // scan output -> gated/normed in place

// ---------------- helpers ----------------
__device__ __forceinline__ float silu_f(float x) {
    return x / (1.0f + expf(-x));
}

// ---------------- GEMM: C[m,n] = sum_k A[m*K+k] * B[n*K+k]  (NT, fp32) ----------------
// BM=BN=128, BK=16, 256 threads, 8x8 per thread. M % 128 == 0, K % 16 == 0; N may be ragged (N % 4 == 0).
__global__ __launch_bounds__(256) void sgemm_nt_kernel(
    const float* __restrict__ A, const float* __restrict__ B, float* __restrict__ C,
    int M, int N, int K)
{
    __shared__ float As[16][132];
    __shared__ float Bs[16][132];

    const int tid = threadIdx.x;
    const int tx = tid & 15;        // n dir
    const int ty = tid >> 4;        // m dir
    const int m0 = blockIdx.y * 128;
    const int n0 = blockIdx.x * 128;

    float acc[8][8];
#pragma unroll
    for (int i = 0; i < 8; i++)
#pragma unroll
        for (int j = 0; j < 8; j++) acc[i][j] = 0.0f;

    for (int k0 = 0; k0 < K; k0 += 16) {
#pragma unroll
        for (int r = 0; r < 2; r++) {
            int f = tid + r * 256;          // 0..511
            int row = f >> 2;
            int kq = (f & 3) * 4;
            float4 va = *(const float4*)&A[(size_t)(m0 + row) * K + k0 + kq];
            As[kq + 0][row] = va.x; As[kq + 1][row] = va.y;
            As[kq + 2][row] = va.z; As[kq + 3][row] = va.w;
            int nrow = n0 + row;
            float4 vb = make_float4(0.f, 0.f, 0.f, 0.f);
            if (nrow < N) vb = *(const float4*)&B[(size_t)nrow * K + k0 + kq];
            Bs[kq + 0][row] = vb.x; Bs[kq + 1][row] = vb.y;
            Bs[kq + 2][row] = vb.z; Bs[kq + 3][row] = vb.w;
        }
        __syncthreads();

#pragma unroll
        for (int k = 0; k < 16; k++) {
            float4 a0 = *(const float4*)&As[k][ty * 8];
            float4 a1 = *(const float4*)&As[k][ty * 8 + 4];
            float4 b0 = *(const float4*)&Bs[k][tx * 8];
            float4 b1 = *(const float4*)&Bs[k][tx * 8 + 4];
            float af[8] = {a0.x, a0.y, a0.z, a0.w, a1.x, a1.y, a1.z, a1.w};
            float bf[8] = {b0.x, b0.y, b0.z, b0.w, b1.x, b1.y, b1.z, b1.w};
#pragma unroll
            for (int i = 0; i < 8; i++)
#pragma unroll
                for (int j = 0; j < 8; j++)
                    acc[i][j] = fmaf(af[i], bf[j], acc[i][j]);
        }
        __syncthreads();
    }

#pragma unroll
    for (int i = 0; i < 8; i++) {
        size_t crow = (size_t)(m0 + ty * 8 + i) * N;
#pragma unroll
        for (int j = 0; j < 8; j += 4) {
            int n = n0 + tx * 8 + j;
            if (n < N) {
                *(float4*)&C[crow + n] =
                    make_float4(acc[i][j], acc[i][j + 1], acc[i][j + 2], acc[i][j + 3]);
            }
        }
    }
}

// ---------------- conv1d (width 4, causal) + bias + SiLU ----------------
__global__ __launch_bounds__(256) void conv_silu_kernel(
    const float* __restrict__ conv_w, const float* __restrict__ conv_b)
{
    size_t idx = (size_t)blockIdx.x * blockDim.x + threadIdx.x;
    if (idx >= (size_t)ROWS * CONVDIM) return;
    int c = (int)(idx % CONVDIM);
    size_t bt = idx / CONVDIM;
    int t = (int)(bt % LL);
    size_t brow0 = (bt - t); // (b*L) base row

    float accv = conv_b[c];
#pragma unroll
    for (int w = 0; w < DCONV; w++) {
        int ts = t - (DCONV - 1) + w;
        if (ts >= 0) {
            accv = fmaf(g_zxbcdt[(brow0 + ts) * (size_t)DPROJ + DSSM + c],
                        conv_w[c * DCONV + w], accv);
        }
    }
    g_xbc[idx] = silu_f(accv);
}

// ---------------- dt softplus + dA precompute ----------------
__global__ __launch_bounds__(256) void dt_kernel(
    const float* __restrict__ dt_bias, const float* __restrict__ A_log)
{
    int idx = blockIdx.x * blockDim.x + threadIdx.x;
    if (idx >= ROWS * NH) return;
    int h = idx % NH;
    int r = idx / NH;
    float raw = g_zxbcdt[(size_t)r * DPROJ + DSSM + CONVDIM + h] + dt_bias[h];
    float dt = (raw > 20.0f) ? raw : log1pf(expf(raw));
    float Aneg = -expf(A_log[h]);
    g_dt[idx] = dt;
    g_dA[idx] = expf(dt * Aneg);
}

// ---------------- selective scan ----------------
// 128 CTAs: (b, h, p-half). 256 threads: warp w -> 4 p's, lane -> 4 n's. State 4x4 regs.
__global__ __launch_bounds__(256) void scan_kernel(const float* __restrict__ Dp)
{
    const int blk = blockIdx.x;        // 0..127
    const int b = blk >> 6;
    const int hh = blk & 63;
    const int h = hh >> 1;
    const int p_base = (hh & 1) * 32;

    const int tid = threadIdx.x;
    const int w = tid >> 5;
    const int lane = tid & 31;
    const int p0 = p_base + w * 4;

    __shared__ float4 sB[2][32];
    __shared__ float4 sC[2][32];
    __shared__ float4 sx[2][8];
    __shared__ float sdt[2], sdA[2];

    float hs[4][4];
#pragma unroll
    for (int i = 0; i < 4; i++)
#pragma unroll
        for (int j = 0; j < 4; j++) hs[i][j] = 0.0f;

    const float Dh = Dp[h];
    const float* base = g_xbc + (size_t)b * LL * CONVDIM;
    const size_t dtbase = (size_t)b * LL * NH + h;
    float* yout = g_y + (size_t)b * LL * DSSM + h * HD;

    // stage 0 preload
    {
        const float* rb = base;
        if (tid < 32)       sB[0][tid]      = *(const float4*)(rb + DSSM + tid * 4);
        else if (tid < 64)  sC[0][tid - 32] = *(const float4*)(rb + DSSM + DSTATE + (tid - 32) * 4);
        else if (tid < 72)  sx[0][tid - 64] = *(const float4*)(rb + h * HD + p_base + (tid - 64) * 4);
        else if (tid == 72) sdt[0] = g_dt[dtbase];
        else if (tid == 73) sdA[0] = g_dA[dtbase];
    }

    for (int t = 0; t < LL; t++) {
        __syncthreads();
        const int cur = t & 1;
        if (t + 1 < LL) {
            const float* rb = base + (size_t)(t + 1) * CONVDIM;
            const int nxt = cur ^ 1;
            if (tid < 32)       sB[nxt][tid]      = *(const float4*)(rb + DSSM + tid * 4);
            else if (tid < 64)  sC[nxt][tid - 32] = *(const float4*)(rb + DSSM + DSTATE + (tid - 32) * 4);
            else if (tid < 72)  sx[nxt][tid - 64] = *(const float4*)(rb + h * HD + p_base + (tid - 64) * 4);
            else if (tid == 72) sdt[nxt] = g_dt[dtbase + (size_t)(t + 1) * NH];
            else if (tid == 73) sdA[nxt] = g_dA[dtbase + (size_t)(t + 1) * NH];
        }

        const float dtv = sdt[cur];
        const float dAv = sdA[cur];
        const float4 Bv = sB[cur][lane];
        const float4 Cv = sC[cur][lane];
        const float4 xv = sx[cur][w];

        const float bb[4] = {Bv.x, Bv.y, Bv.z, Bv.w};
        const float cc[4] = {Cv.x, Cv.y, Cv.z, Cv.w};
        const float xx[4] = {xv.x, xv.y, xv.z, xv.w};

        float acc[4] = {0.f, 0.f, 0.f, 0.f};
#pragma unroll
        for (int i = 0; i < 4; i++) {
            const float dtx = dtv * xx[i];
#pragma unroll
            for (int j = 0; j < 4; j++) {
                hs[i][j] = fmaf(hs[i][j], dAv, dtx * bb[j]);
                acc[i] = fmaf(hs[i][j], cc[j], acc[i]);
            }
        }
        // reduce each acc over all 32 lanes (n dimension)
#pragma unroll
        for (int i = 0; i < 4; i++) {
            float a = acc[i];
            a += __shfl_xor_sync(0xffffffffu, a, 16);
            a += __shfl_xor_sync(0xffffffffu, a, 8);
            a += __shfl_xor_sync(0xffffffffu, a, 4);
            a += __shfl_xor_sync(0xffffffffu, a, 2);
            a += __shfl_xor_sync(0xffffffffu, a, 1);
            acc[i] = a;
        }
        if (lane < 4) {
            float res = (lane == 0) ? acc[0] : (lane == 1) ? acc[1] : (lane == 2) ? acc[2] : acc[3];
            float xval = (lane == 0) ? xv.x : (lane == 1) ? xv.y : (lane == 2) ? xv.z : xv.w;
            yout[(size_t)t * DSSM + p0 + lane] = fmaf(Dh, xval, res);
        }
    }
}

// ---------------- gate (silu(z)) + RMSNorm (in place on g_y) ----------------
__global__ __launch_bounds__(256) void gate_rmsnorm_kernel(const float* __restrict__ norm_w)
{
    const int row = blockIdx.x;      // 0..8191
    const int tid = threadIdx.x;
    const int w = tid >> 5, lane = tid & 31;

    float vals[8];
    float ss = 0.f;
#pragma unroll
    for (int i = 0; i < 8; i++) {
        int e = i * 256 + tid;
        float z = g_zxbcdt[(size_t)row * DPROJ + e];
        float yv = g_y[(size_t)row * DSSM + e];
        float g = yv * silu_f(z);
        vals[i] = g;
        ss = fmaf(g, g, ss);
    }
    ss += __shfl_xor_sync(0xffffffffu, ss, 16);
    ss += __shfl_xor_sync(0xffffffffu, ss, 8);
    ss += __shfl_xor_sync(0xffffffffu, ss, 4);
    ss += __shfl_xor_sync(0xffffffffu, ss, 2);
    ss += __shfl_xor_sync(0xffffffffu, ss, 1);

    __shared__ float red[8];
    __shared__ float sscale;
    if (lane == 0) red[w] = ss;
    __syncthreads();
    if (tid == 0) {
        float s = 0.f;
#pragma unroll
        for (int k = 0; k < 8; k++) s += red[k];
        sscale = rsqrtf(s / (float)DSSM + EPSV);
    }
    __syncthreads();
    const float scale = sscale;
#pragma unroll
    for (int i = 0; i < 8; i++) {
        int e = i * 256 + tid;
        g_y[(size_t)row * DSSM + e] = vals[i] * scale * norm_w[e];
    }
}

// ---------------- entry ----------------
extern "C" void kernel_launch(void* const* d_in, const int* in_sizes, int n_in,
                              void* d_out, int out_size)
{
    const float* u       = (const float*)d_in[0];  // [2,4096,1024]
    const float* W_in    = (const float*)d_in[1];  // [4384,1024]
    const float* conv_w  = (const float*)d_in[2];  // [2304,4]
    const float* conv_b  = (const float*)d_in[3];  // [2304]
    const float* dt_bias = (const float*)d_in[4];  // [32]
    const float* A_log   = (const float*)d_in[5];  // [32]
    const float* Dp      = (const float*)d_in[6];  // [32]
    const float* norm_w  = (const float*)d_in[7];  // [2048]
    const float* W_out   = (const float*)d_in[8];  // [1024,2048]
    float* out = (float*)d_out;                    // [2,4096,1024]

    float* zx;  cudaGetSymbolAddress((void**)&zx,  g_zxbcdt);
    float* gy;  cudaGetSymbolAddress((void**)&gy,  g_y);

    // 1) in-projection: zxbcdt = u @ W_in^T
    {
        dim3 grid((DPROJ + 127) / 128, ROWS / 128);
        sgemm_nt_kernel<<<grid, 256>>>(u, W_in, zx, ROWS, DPROJ, DMODEL);
    }
    // 2) conv + silu
    {
        size_t total = (size_t)ROWS * CONVDIM;
        conv_silu_kernel<<<(unsigned)((total + 255) / 256), 256>>>(conv_w, conv_b);
    }
    // 3) dt softplus + dA
    dt_kernel<<<(ROWS * NH + 255) / 256, 256>>>(dt_bias, A_log);
    // 4) selective scan
    scan_kernel<<<128, 256>>>(Dp);
    // 5) gate + rmsnorm (in place on g_y)
    gate_rmsnorm_kernel<<<ROWS, 256>>>(norm_w);
    // 6) out-projection: out = g @ W_out^T
    {
        dim3 grid(DMODEL / 128, ROWS / 128);
        sgemm_nt_kernel<<<grid, 256>>>(gy, W_out, out, ROWS, DMODEL, DSSM);
    }
}